// round 13
// baseline (speedup 1.0000x reference)
#include <cuda_runtime.h>
#include <cuda_bf16.h>
#include <math.h>
#include <stdint.h>

#define Bsz  512
#define Lsz  512
#define Fsz  128
#define G4L  2048          // 4*L
#define KSPL 256           // K per split half (K total = 512 after Wcomb fusion)
#define Tt   512
#define OSTR (Tt * Fsz)    // out stride between batch rows
#define NCTA 128
#define NTHR 512

// ---- smem layout (dynamic, 128B-aligned base) ----
#define BPITCH  528                       // 512B data + 16B pad (conflict-free)
#define BTILESZ (128 * BPITCH)            // 67,584 per half
#define OFF_B   0
#define OFF_H2S (2 * BTILESZ)             // 135,168
#define OFF_RED (OFF_H2S + 4 * Lsz * 4)   // 143,360
#define SMEM_ALLOC (OFF_RED + 16 * 128 * 4 + 128)   // 151,680

// ---------------- device scratch ---------------------------------------------
__device__ __nv_bfloat16 g_Ah[Bsz * Lsz];    // h state (hi), [b][l], stride 512
__device__ __nv_bfloat16 g_Al[Bsz * Lsz];    // (lo)
__device__ __nv_bfloat16 g_Bh[G4L * Lsz];    // Wcomb [j][k] (hi)
__device__ __nv_bfloat16 g_Bl[G4L * Lsz];    // (lo)
__device__ float g_WdT[Lsz * Fsz];           // [l][f] W_dense^T (fp32, out dense)
__device__ float g_bsum[G4L];                // fused bias: b_ih+b_hh+W_ih@b_d
__device__ float g_c[Bsz * Lsz];
__device__ float g_gp0[Bsz * G4L];           // partials half 0 (also Wcomb fp32 temp)
__device__ float g_gp1[Bsz * G4L];           // partials half 1
__device__ unsigned g_barcnt;
__device__ volatile unsigned g_bargen;

// ---------------- PTX helpers -------------------------------------------------
__device__ __forceinline__ uint32_t smem_u32(const void* p) {
    uint32_t a;
    asm("{ .reg .u64 t; cvta.to.shared.u64 t, %1; cvt.u32.u64 %0, t; }"
        : "=r"(a) : "l"(p));
    return a;
}
__device__ __forceinline__ void cpa16(uint32_t s, const void* g) {
    asm volatile("cp.async.cg.shared.global [%0], [%1], 16;"
                 :: "r"(s), "l"(g) : "memory");
}
__device__ __forceinline__ void cpa_commit() {
    asm volatile("cp.async.commit_group;" ::: "memory");
}
__device__ __forceinline__ void cpa_wait0() {
    asm volatile("cp.async.wait_group 0;" ::: "memory");
}
__device__ __forceinline__ void ldsm4(uint32_t* r, uint32_t addr) {
    asm volatile("ldmatrix.sync.aligned.m8n8.x4.shared.b16 {%0,%1,%2,%3}, [%4];"
                 : "=r"(r[0]), "=r"(r[1]), "=r"(r[2]), "=r"(r[3]) : "r"(addr));
}
__device__ __forceinline__ void mma16816(float* c, const uint32_t* a,
                                         uint32_t b0, uint32_t b1) {
    asm volatile(
        "mma.sync.aligned.m16n8k16.row.col.f32.bf16.bf16.f32 "
        "{%0,%1,%2,%3}, {%4,%5,%6,%7}, {%8,%9}, {%0,%1,%2,%3};"
        : "+f"(c[0]), "+f"(c[1]), "+f"(c[2]), "+f"(c[3])
        : "r"(a[0]), "r"(a[1]), "r"(a[2]), "r"(a[3]), "r"(b0), "r"(b1));
}
// L2-coherent loads (bypass L1 — cross-CTA data in a persistent kernel)
__device__ __forceinline__ uint32_t ldcg32(const void* p) {
    uint32_t v;
    asm volatile("ld.global.cg.u32 %0, [%1];" : "=r"(v) : "l"(p));
    return v;
}
__device__ __forceinline__ float4 ldcg128(const float* p) {
    float4 v;
    asm volatile("ld.global.cg.v4.f32 {%0,%1,%2,%3}, [%4];"
                 : "=f"(v.x), "=f"(v.y), "=f"(v.z), "=f"(v.w) : "l"(p));
    return v;
}

// ---------------- grid-wide barrier (pure spin) --------------------------------
__device__ __forceinline__ void gridbar() {
    __syncthreads();
    if (threadIdx.x == 0) {
        unsigned gen = g_bargen;
        __threadfence();
        if (atomicAdd(&g_barcnt, 1u) == NCTA - 1) {
            g_barcnt = 0;
            __threadfence();
            g_bargen = gen + 1;
        } else {
            while (g_bargen == gen) { }
            __threadfence();
        }
    }
    __syncthreads();
}

// ---------------- math helpers -------------------------------------------------
__device__ __forceinline__ void split_bf16(float x, __nv_bfloat16& hi,
                                           __nv_bfloat16& lo) {
    hi = __float2bfloat16(x);
    lo = __float2bfloat16(x - __bfloat162float(hi));
}
__device__ __forceinline__ float fsigmoid(float x) {
    return __fdividef(1.0f, 1.0f + __expf(-x));
}
__device__ __forceinline__ float ftanh_(float x) {
    return 1.0f - __fdividef(2.0f, __expf(2.0f * x) + 1.0f);
}

// ---------------- dense (out only): out[b][t][:] = h2s @ WdT + b_dense ---------
__device__ __forceinline__ void dense_part(const float* h2s, float* red,
                                           const float* __restrict__ b_dense,
                                           int b0, float* __restrict__ out, int t) {
    const int tid = threadIdx.x;
    const int f = tid & 127, gg = tid >> 7;     // gg in {0..3}
    float a0 = 0.f, a1 = 0.f, a2 = 0.f, a3 = 0.f;
    const int l0 = gg * 128;
#pragma unroll 4
    for (int l4 = 0; l4 < 128; l4 += 4) {
        const int l = l0 + l4;
        const float4 h0v = *(const float4*)&h2s[0 * Lsz + l];
        const float4 h1v = *(const float4*)&h2s[1 * Lsz + l];
        const float4 h2v = *(const float4*)&h2s[2 * Lsz + l];
        const float4 h3v = *(const float4*)&h2s[3 * Lsz + l];
        const float w0 = __ldg(&g_WdT[(l + 0) * Fsz + f]);
        const float w1 = __ldg(&g_WdT[(l + 1) * Fsz + f]);
        const float w2 = __ldg(&g_WdT[(l + 2) * Fsz + f]);
        const float w3 = __ldg(&g_WdT[(l + 3) * Fsz + f]);
        a0 = fmaf(h0v.x, w0, a0); a1 = fmaf(h1v.x, w0, a1);
        a2 = fmaf(h2v.x, w0, a2); a3 = fmaf(h3v.x, w0, a3);
        a0 = fmaf(h0v.y, w1, a0); a1 = fmaf(h1v.y, w1, a1);
        a2 = fmaf(h2v.y, w1, a2); a3 = fmaf(h3v.y, w1, a3);
        a0 = fmaf(h0v.z, w2, a0); a1 = fmaf(h1v.z, w2, a1);
        a2 = fmaf(h2v.z, w2, a2); a3 = fmaf(h3v.z, w2, a3);
        a0 = fmaf(h0v.w, w3, a0); a1 = fmaf(h1v.w, w3, a1);
        a2 = fmaf(h2v.w, w3, a2); a3 = fmaf(h3v.w, w3, a3);
    }
    red[(gg * 4 + 0) * 128 + f] = a0;
    red[(gg * 4 + 1) * 128 + f] = a1;
    red[(gg * 4 + 2) * 128 + f] = a2;
    red[(gg * 4 + 3) * 128 + f] = a3;
    __syncthreads();
    if (gg == 0) {
        const float bb = b_dense[f];
#pragma unroll
        for (int r = 0; r < 4; ++r) {
            const float v = red[r * 128 + f] + red[(4 + r) * 128 + f]
                          + red[(8 + r) * 128 + f] + red[(12 + r) * 128 + f] + bb;
            out[(size_t)(b0 + r) * OSTR + (size_t)t * Fsz + f] = v;
        }
    }
    __syncthreads();
}

// ---------------- the single persistent kernel ---------------------------------
__global__ void __launch_bounds__(NTHR, 1)
lstm_kernel(const float* __restrict__ h0, const float* __restrict__ c0,
            const float* __restrict__ W_ih, const float* __restrict__ W_hh,
            const float* __restrict__ b_ih, const float* __restrict__ b_hh,
            const float* __restrict__ W_dense, const float* __restrict__ b_dense,
            float* __restrict__ out) {
    extern __shared__ char dsm[];
    const uint32_t smb0 = smem_u32(dsm);
    const uint32_t smb = (smb0 + 127u) & ~127u;
    char* sbase = dsm + (smb - smb0);
    float* h2s = (float*)(sbase + OFF_H2S);
    float* red = (float*)(sbase + OFF_RED);

    const int bid = blockIdx.x, tid = threadIdx.x;
    const int wid = tid >> 5, lane = tid & 31;
    const int b0 = bid * 4;

    // gates unit: split-K halves x 64 C tiles of 128x128 (K total = 512)
    const int ks   = bid & 1;
    const int tile = bid >> 1;
    const int m0   = (tile >> 4) * 128;
    const int n0   = (tile & 15) * 128;
    const int kb   = ks * KSPL;
    float* gp = ks ? g_gp1 : g_gp0;

    // warp tile 32(m) x 32(n); warp grid 4x4
    const int wm = (wid >> 2) * 32;
    const int wn = (wid & 3) * 32;
    const int gr = lane >> 2, gc = (lane & 3) * 2;   // mma A-fragment lane map
    const uint32_t laneB = (uint32_t)((lane & 7) + ((lane >> 4) << 3)) * BPITCH
                         + (uint32_t)((lane >> 3) & 1) * 16;

    // ---- P1a: WdT, fused bias, h0 split, c0 copy ----
    {
        const int N1 = Lsz * Fsz;              // WdT
        const int N2 = N1 + G4L;               // fused bias
        const int N3 = N2 + Bsz * Lsz;         // h0 -> g_Ah/g_Al
        const int N4 = N3 + Bsz * Lsz;         // c0 -> g_c
        for (int idx = bid * NTHR + tid; idx < N4; idx += NCTA * NTHR) {
            if (idx < N1) {
                const int l = idx / Fsz, f = idx % Fsz;
                g_WdT[idx] = W_dense[(size_t)f * Lsz + l];
            } else if (idx < N2) {
                const int j = idx - N1;
                float acc = b_ih[j] + b_hh[j];
                for (int f = 0; f < Fsz; ++f)
                    acc = fmaf(W_ih[(size_t)j * Fsz + f], b_dense[f], acc);
                g_bsum[j] = acc;
            } else if (idx < N3) {
                const int i = idx - N2;
                __nv_bfloat16 hi, lo;
                split_bf16(h0[i], hi, lo);
                g_Ah[i] = hi;
                g_Al[i] = lo;
            } else {
                const int i = idx - N3;
                g_c[i] = c0[i];
            }
        }
    }

    // ---- P1b: Wcomb[j][l] = W_hh[j][l] + sum_f W_ih[j][f]*W_dense[f][l] ----
    // (fp32 into g_gp0 temp; 65536 threads -> j = gt>>5, 16 l's per thread)
    {
        const int gt = bid * NTHR + tid;       // 0..65535
        const int j  = gt >> 5;
        const int lb = gt & 31;
        float acc[16];
#pragma unroll
        for (int i = 0; i < 16; ++i)
            acc[i] = W_hh[(size_t)j * Lsz + lb + i * 32];
        for (int f = 0; f < Fsz; ++f) {
            const float wih = W_ih[(size_t)j * Fsz + f];
            const float* wd = W_dense + (size_t)f * Lsz + lb;
#pragma unroll
            for (int i = 0; i < 16; ++i)
                acc[i] = fmaf(wih, wd[i * 32], acc[i]);
        }
#pragma unroll
        for (int i = 0; i < 16; ++i)
            g_gp0[(size_t)j * Lsz + lb + i * 32] = acc[i];
    }
    gridbar();

    // ---- P1c: split Wcomb fp32 -> bf16 hi/lo ----
    {
        const int NT = G4L * Lsz;              // 1,048,576
        for (int idx = bid * NTHR + tid; idx < NT; idx += NCTA * NTHR) {
            __nv_bfloat16 hi, lo;
            split_bf16(g_gp0[idx], hi, lo);
            g_Bh[idx] = hi;
            g_Bl[idx] = lo;
        }
    }
    gridbar();

    // ---- load resident B tile (once): 2 halves x 128 rows x 512B ----
    {
#pragma unroll
        for (int i = 0; i < 16; ++i) {
            const int idx = tid + i * NTHR;    // 0..8191
            const int half = idx >= 4096;
            const int j = idx & 4095;
            const int row = j >> 5, q = j & 31;
            const __nv_bfloat16* src =
                (half ? g_Bl : g_Bh) + (size_t)(n0 + row) * Lsz + kb + q * 8;
            const uint32_t dst = smb + OFF_B + (uint32_t)half * BTILESZ
                               + (uint32_t)row * BPITCH + (uint32_t)q * 16;
            cpa16(dst, src);
        }
        cpa_commit();
        cpa_wait0();
        __syncthreads();
    }

    // per-thread A fragment base pointers (addresses constant across steps)
    const __nv_bfloat16* aBh = g_Ah + (size_t)(m0 + wm + gr) * Lsz + kb + gc;
    const __nv_bfloat16* aBl = g_Al + (size_t)(m0 + wm + gr) * Lsz + kb + gc;

    // ---- main recurrence ----
    for (int t = 0; t < Tt; ++t) {
        float acc[2][4][4];
#pragma unroll
        for (int a = 0; a < 2; ++a)
#pragma unroll
            for (int b = 0; b < 4; ++b)
#pragma unroll
                for (int q = 0; q < 4; ++q) acc[a][b][q] = 0.f;

#pragma unroll 4
        for (int kk = 0; kk < 16; ++kk) {
            const int kc = kk * 16;
            uint32_t ah[2][4], al[2][4], bh[2][4], bl[2][4];
#pragma unroll
            for (int mf = 0; mf < 2; ++mf) {
                const __nv_bfloat16* ph = aBh + (size_t)(mf * 16) * Lsz + kc;
                const __nv_bfloat16* pl = aBl + (size_t)(mf * 16) * Lsz + kc;
                ah[mf][0] = ldcg32(ph);
                ah[mf][1] = ldcg32(ph + 8 * Lsz);
                ah[mf][2] = ldcg32(ph + 8);
                ah[mf][3] = ldcg32(ph + 8 * Lsz + 8);
                al[mf][0] = ldcg32(pl);
                al[mf][1] = ldcg32(pl + 8 * Lsz);
                al[mf][2] = ldcg32(pl + 8);
                al[mf][3] = ldcg32(pl + 8 * Lsz + 8);
            }
#pragma unroll
            for (int gg = 0; gg < 2; ++gg) {
                const uint32_t ro = smb + OFF_B
                                  + (uint32_t)(wn + gg * 16) * BPITCH + laneB
                                  + (uint32_t)kk * 32;
                ldsm4(bh[gg], ro);
                ldsm4(bl[gg], ro + BTILESZ);
            }
            // pass 1: Ah * Bh
#pragma unroll
            for (int mf = 0; mf < 2; ++mf)
#pragma unroll
                for (int nf = 0; nf < 4; ++nf)
                    mma16816(acc[mf][nf], ah[mf],
                             bh[nf >> 1][(nf & 1) * 2], bh[nf >> 1][(nf & 1) * 2 + 1]);
            // pass 2: Ah * Bl
#pragma unroll
            for (int mf = 0; mf < 2; ++mf)
#pragma unroll
                for (int nf = 0; nf < 4; ++nf)
                    mma16816(acc[mf][nf], ah[mf],
                             bl[nf >> 1][(nf & 1) * 2], bl[nf >> 1][(nf & 1) * 2 + 1]);
            // pass 3: Al * Bh
#pragma unroll
            for (int mf = 0; mf < 2; ++mf)
#pragma unroll
                for (int nf = 0; nf < 4; ++nf)
                    mma16816(acc[mf][nf], al[mf],
                             bh[nf >> 1][(nf & 1) * 2], bh[nf >> 1][(nf & 1) * 2 + 1]);
        }

        // epilogue: write 128x128 partial tile (each warp 32x32)
#pragma unroll
        for (int mf = 0; mf < 2; ++mf) {
            const int r0 = m0 + wm + mf * 16 + gr;
#pragma unroll
            for (int nf = 0; nf < 4; ++nf) {
                const int col = n0 + wn + nf * 8 + gc;
                float* p = gp + (size_t)r0 * G4L + col;
                *(float2*)p             = make_float2(acc[mf][nf][0], acc[mf][nf][1]);
                *(float2*)(p + 8 * G4L) = make_float2(acc[mf][nf][2], acc[mf][nf][3]);
            }
        }
        gridbar();

        // ----- LSTM cell for rows b0..b0+3: one l-quad per thread -----
        {
            const int e = tid * 4;                  // 0..2044
            const int r = e >> 9, l = e & 511;
            const int b = b0 + r;
            const size_t gb = (size_t)b * G4L + l;
            const float4 i0 = ldcg128(&g_gp0[gb]);
            const float4 i1 = ldcg128(&g_gp1[gb]);
            const float4 f0 = ldcg128(&g_gp0[gb + 512]);
            const float4 f1 = ldcg128(&g_gp1[gb + 512]);
            const float4 g0 = ldcg128(&g_gp0[gb + 1024]);
            const float4 g1 = ldcg128(&g_gp1[gb + 1024]);
            const float4 o0 = ldcg128(&g_gp0[gb + 1536]);
            const float4 o1 = ldcg128(&g_gp1[gb + 1536]);
            const float4 bi = *(const float4*)&g_bsum[l];
            const float4 bf = *(const float4*)&g_bsum[l + 512];
            const float4 bg = *(const float4*)&g_bsum[l + 1024];
            const float4 bo = *(const float4*)&g_bsum[l + 1536];
            const size_t hc = (size_t)b * Lsz + l;
            float4 cc = *(const float4*)&g_c[hc];
            float h2q[4];
            {
                const float gi[4] = {i0.x + i1.x + bi.x, i0.y + i1.y + bi.y,
                                     i0.z + i1.z + bi.z, i0.w + i1.w + bi.w};
                const float gf[4] = {f0.x + f1.x + bf.x, f0.y + f1.y + bf.y,
                                     f0.z + f1.z + bf.z, f0.w + f1.w + bf.w};
                const float gg2[4] = {g0.x + g1.x + bg.x, g0.y + g1.y + bg.y,
                                      g0.z + g1.z + bg.z, g0.w + g1.w + bg.w};
                const float go[4] = {o0.x + o1.x + bo.x, o0.y + o1.y + bo.y,
                                     o0.z + o1.z + bo.z, o0.w + o1.w + bo.w};
                float* cp = &cc.x;
#pragma unroll
                for (int q = 0; q < 4; ++q) {
                    const float c2 = fsigmoid(gf[q]) * cp[q]
                                   + fsigmoid(gi[q]) * ftanh_(gg2[q]);
                    h2q[q] = fsigmoid(go[q]) * ftanh_(c2);
                    cp[q] = c2;
                }
            }
            *(float4*)&g_c[hc] = cc;
            *(float4*)&h2s[r * Lsz + l] = make_float4(h2q[0], h2q[1], h2q[2], h2q[3]);
            // packed bf16 hi/lo state stores (2 x STG.64)
            __nv_bfloat162 ph[2], pl[2];
#pragma unroll
            for (int q = 0; q < 2; ++q) {
                __nv_bfloat16 h0b, l0b, h1b, l1b;
                split_bf16(h2q[q * 2 + 0], h0b, l0b);
                split_bf16(h2q[q * 2 + 1], h1b, l1b);
                ph[q].x = h0b; ph[q].y = h1b;
                pl[q].x = l0b; pl[q].y = l1b;
            }
            *(uint2*)&g_Ah[hc] = *(uint2*)ph;
            *(uint2*)&g_Al[hc] = *(uint2*)pl;
        }
        __syncthreads();
        dense_part(h2s, red, b_dense, b0, out, t);
        gridbar();
    }
}

// ---------------- host ----------------------------------------------------------
extern "C" void kernel_launch(void* const* d_in, const int* in_sizes, int n_in,
                              void* d_out, int out_size) {
    const float* h0      = (const float*)d_in[0];
    const float* c0      = (const float*)d_in[1];
    const float* W_ih    = (const float*)d_in[2];
    const float* W_hh    = (const float*)d_in[3];
    const float* b_ih    = (const float*)d_in[4];
    const float* b_hh    = (const float*)d_in[5];
    const float* W_dense = (const float*)d_in[6];
    const float* b_dense = (const float*)d_in[7];
    float* out = (float*)d_out;

    cudaFuncSetAttribute(lstm_kernel,
                         cudaFuncAttributeMaxDynamicSharedMemorySize, SMEM_ALLOC);
    lstm_kernel<<<NCTA, NTHR, SMEM_ALLOC>>>(h0, c0, W_ih, W_hh, b_ih, b_hh,
                                            W_dense, b_dense, out);
}

// round 14
// speedup vs baseline: 1.6784x; 1.6784x over previous
#include <cuda_runtime.h>
#include <cuda_bf16.h>
#include <math.h>
#include <stdint.h>

#define Bsz  512
#define Lsz  512
#define Fsz  128
#define G4L  2048          // 4*L
#define KSPL 256           // K per split half (K total = 512 after Wcomb fusion)
#define Tt   512
#define OSTR (Tt * Fsz)    // out stride between batch rows
#define NCTA 128
#define NTHR 512

// ---- smem layout (dynamic, 128B-aligned base) ----
#define BPITCH  528                       // 512B data + 16B pad (conflict-free)
#define BTILESZ (128 * BPITCH)            // 67,584 per half
#define APITCH  80                        // 64B data + 16B pad
#define GSTRIP  2560                      // 32 rows x 80B (one half, one group)
#define GBUF    (2 * GSTRIP)              // hi+lo = 5,120 per group buffer
#define OFF_B   0
#define OFF_A   (2 * BTILESZ)             // 135,168 (4 groups x 2 bufs x 5,120)
#define OFF_H2S (OFF_A + 8 * GBUF)        // 176,128
#define OFF_RED (OFF_H2S + 4 * Lsz * 4)   // 184,320
#define SMEM_ALLOC (OFF_RED + 16 * 128 * 4 + 128)   // 192,640

// ---------------- device scratch ---------------------------------------------
__device__ __nv_bfloat16 g_Ah[Bsz * Lsz];    // h state (hi), [b][l], stride 512
__device__ __nv_bfloat16 g_Al[Bsz * Lsz];    // (lo)
__device__ __nv_bfloat16 g_Bh[G4L * Lsz];    // Wcomb [j][k] (hi)
__device__ __nv_bfloat16 g_Bl[G4L * Lsz];    // (lo)
__device__ float g_WdT[Lsz * Fsz];           // [l][f] W_dense^T (fp32, out dense)
__device__ float g_bsum[G4L];                // fused bias: b_ih+b_hh+W_ih@b_d
__device__ float g_c[Bsz * Lsz];
__device__ float g_gp0[Bsz * G4L];           // partials half 0 (also Wcomb fp32 temp)
__device__ float g_gp1[Bsz * G4L];           // partials half 1
__device__ unsigned g_barcnt;
__device__ volatile unsigned g_bargen;

// ---------------- PTX helpers -------------------------------------------------
__device__ __forceinline__ uint32_t smem_u32(const void* p) {
    uint32_t a;
    asm("{ .reg .u64 t; cvta.to.shared.u64 t, %1; cvt.u32.u64 %0, t; }"
        : "=r"(a) : "l"(p));
    return a;
}
__device__ __forceinline__ void cpa16(uint32_t s, const void* g) {
    asm volatile("cp.async.cg.shared.global [%0], [%1], 16;"
                 :: "r"(s), "l"(g) : "memory");
}
__device__ __forceinline__ void cpa_commit() {
    asm volatile("cp.async.commit_group;" ::: "memory");
}
__device__ __forceinline__ void cpa_wait0() {
    asm volatile("cp.async.wait_group 0;" ::: "memory");
}
__device__ __forceinline__ void ldsm4(uint32_t* r, uint32_t addr) {
    asm volatile("ldmatrix.sync.aligned.m8n8.x4.shared.b16 {%0,%1,%2,%3}, [%4];"
                 : "=r"(r[0]), "=r"(r[1]), "=r"(r[2]), "=r"(r[3]) : "r"(addr));
}
__device__ __forceinline__ void mma16816(float* c, const uint32_t* a,
                                         uint32_t b0, uint32_t b1) {
    asm volatile(
        "mma.sync.aligned.m16n8k16.row.col.f32.bf16.bf16.f32 "
        "{%0,%1,%2,%3}, {%4,%5,%6,%7}, {%8,%9}, {%0,%1,%2,%3};"
        : "+f"(c[0]), "+f"(c[1]), "+f"(c[2]), "+f"(c[3])
        : "r"(a[0]), "r"(a[1]), "r"(a[2]), "r"(a[3]), "r"(b0), "r"(b1));
}
// L2-coherent load (cross-CTA data in a persistent kernel)
__device__ __forceinline__ float4 ldcg128(const float* p) {
    float4 v;
    asm volatile("ld.global.cg.v4.f32 {%0,%1,%2,%3}, [%4];"
                 : "=f"(v.x), "=f"(v.y), "=f"(v.z), "=f"(v.w) : "l"(p));
    return v;
}

// ---------------- grid-wide barrier (pure spin) --------------------------------
__device__ __forceinline__ void gridbar() {
    __syncthreads();
    if (threadIdx.x == 0) {
        unsigned gen = g_bargen;
        __threadfence();
        if (atomicAdd(&g_barcnt, 1u) == NCTA - 1) {
            g_barcnt = 0;
            __threadfence();
            g_bargen = gen + 1;
        } else {
            while (g_bargen == gen) { }
            __threadfence();
        }
    }
    __syncthreads();
}

// ---------------- math helpers -------------------------------------------------
__device__ __forceinline__ void split_bf16(float x, __nv_bfloat16& hi,
                                           __nv_bfloat16& lo) {
    hi = __float2bfloat16(x);
    lo = __float2bfloat16(x - __bfloat162float(hi));
}
__device__ __forceinline__ float fsigmoid(float x) {
    return __fdividef(1.0f, 1.0f + __expf(-x));
}
__device__ __forceinline__ float ftanh_(float x) {
    return 1.0f - __fdividef(2.0f, __expf(2.0f * x) + 1.0f);
}

// ---------------- dense (out only): out[b][t][:] = h2s @ WdT + b_dense ---------
__device__ __forceinline__ void dense_part(const float* h2s, float* red,
                                           const float* __restrict__ b_dense,
                                           int b0, float* __restrict__ out, int t) {
    const int tid = threadIdx.x;
    const int f = tid & 127, gg = tid >> 7;     // gg in {0..3}
    float a0 = 0.f, a1 = 0.f, a2 = 0.f, a3 = 0.f;
    const int l0 = gg * 128;
#pragma unroll 4
    for (int l4 = 0; l4 < 128; l4 += 4) {
        const int l = l0 + l4;
        const float4 h0v = *(const float4*)&h2s[0 * Lsz + l];
        const float4 h1v = *(const float4*)&h2s[1 * Lsz + l];
        const float4 h2v = *(const float4*)&h2s[2 * Lsz + l];
        const float4 h3v = *(const float4*)&h2s[3 * Lsz + l];
        const float w0 = __ldg(&g_WdT[(l + 0) * Fsz + f]);
        const float w1 = __ldg(&g_WdT[(l + 1) * Fsz + f]);
        const float w2 = __ldg(&g_WdT[(l + 2) * Fsz + f]);
        const float w3 = __ldg(&g_WdT[(l + 3) * Fsz + f]);
        a0 = fmaf(h0v.x, w0, a0); a1 = fmaf(h1v.x, w0, a1);
        a2 = fmaf(h2v.x, w0, a2); a3 = fmaf(h3v.x, w0, a3);
        a0 = fmaf(h0v.y, w1, a0); a1 = fmaf(h1v.y, w1, a1);
        a2 = fmaf(h2v.y, w1, a2); a3 = fmaf(h3v.y, w1, a3);
        a0 = fmaf(h0v.z, w2, a0); a1 = fmaf(h1v.z, w2, a1);
        a2 = fmaf(h2v.z, w2, a2); a3 = fmaf(h3v.z, w2, a3);
        a0 = fmaf(h0v.w, w3, a0); a1 = fmaf(h1v.w, w3, a1);
        a2 = fmaf(h2v.w, w3, a2); a3 = fmaf(h3v.w, w3, a3);
    }
    red[(gg * 4 + 0) * 128 + f] = a0;
    red[(gg * 4 + 1) * 128 + f] = a1;
    red[(gg * 4 + 2) * 128 + f] = a2;
    red[(gg * 4 + 3) * 128 + f] = a3;
    __syncthreads();
    if (gg == 0) {
        const float bb = b_dense[f];
#pragma unroll
        for (int r = 0; r < 4; ++r) {
            const float v = red[r * 128 + f] + red[(4 + r) * 128 + f]
                          + red[(8 + r) * 128 + f] + red[(12 + r) * 128 + f] + bb;
            out[(size_t)(b0 + r) * OSTR + (size_t)t * Fsz + f] = v;
        }
    }
    __syncthreads();
}

// ---------------- the single persistent kernel ---------------------------------
__global__ void __launch_bounds__(NTHR, 1)
lstm_kernel(const float* __restrict__ h0, const float* __restrict__ c0,
            const float* __restrict__ W_ih, const float* __restrict__ W_hh,
            const float* __restrict__ b_ih, const float* __restrict__ b_hh,
            const float* __restrict__ W_dense, const float* __restrict__ b_dense,
            float* __restrict__ out) {
    extern __shared__ char dsm[];
    const uint32_t smb0 = smem_u32(dsm);
    const uint32_t smb = (smb0 + 127u) & ~127u;
    char* sbase = dsm + (smb - smb0);
    float* h2s = (float*)(sbase + OFF_H2S);
    float* red = (float*)(sbase + OFF_RED);

    const int bid = blockIdx.x, tid = threadIdx.x;
    const int wid = tid >> 5, lane = tid & 31;
    const int b0 = bid * 4;

    // gates unit: split-K halves x 64 C tiles of 128x128 (K total = 512)
    const int ks   = bid & 1;
    const int tile = bid >> 1;
    const int m0   = (tile >> 4) * 128;
    const int n0   = (tile & 15) * 128;
    const int kb   = ks * KSPL;
    float* gp = ks ? g_gp1 : g_gp0;

    // warp-group decomposition: group g = wid>>2 owns A rows [g*32, g*32+32)
    const int g      = wid >> 2;
    const int wg_tid = tid & 127;
    const int wm = g * 32;
    const int wn = (wid & 3) * 32;
    const uint32_t laneA = (uint32_t)(lane & 15) * APITCH + (uint32_t)(lane >> 4) * 16;
    const uint32_t laneB = (uint32_t)((lane & 7) + ((lane >> 4) << 3)) * BPITCH
                         + (uint32_t)((lane >> 3) & 1) * 16;
    const uint32_t barid = 1 + g;

    // ---- P1a: WdT, fused bias, h0 split, c0 copy ----
    {
        const int N1 = Lsz * Fsz;              // WdT
        const int N2 = N1 + G4L;               // fused bias
        const int N3 = N2 + Bsz * Lsz;         // h0 -> g_Ah/g_Al
        const int N4 = N3 + Bsz * Lsz;         // c0 -> g_c
        for (int idx = bid * NTHR + tid; idx < N4; idx += NCTA * NTHR) {
            if (idx < N1) {
                const int l = idx / Fsz, f = idx % Fsz;
                g_WdT[idx] = W_dense[(size_t)f * Lsz + l];
            } else if (idx < N2) {
                const int j = idx - N1;
                float acc = b_ih[j] + b_hh[j];
                for (int f = 0; f < Fsz; ++f)
                    acc = fmaf(W_ih[(size_t)j * Fsz + f], b_dense[f], acc);
                g_bsum[j] = acc;
            } else if (idx < N3) {
                const int i = idx - N2;
                __nv_bfloat16 hi, lo;
                split_bf16(h0[i], hi, lo);
                g_Ah[i] = hi;
                g_Al[i] = lo;
            } else {
                const int i = idx - N3;
                g_c[i] = c0[i];
            }
        }
    }

    // ---- P1b: Wcomb[j][l] = W_hh[j][l] + sum_f W_ih[j][f]*W_dense[f][l] ----
    // (fp32 into g_gp0 temp; 65536 threads -> j = gt>>5, 16 l's per thread)
    {
        const int gt = bid * NTHR + tid;       // 0..65535
        const int j  = gt >> 5;
        const int lb = gt & 31;
        float acc[16];
#pragma unroll
        for (int i = 0; i < 16; ++i)
            acc[i] = W_hh[(size_t)j * Lsz + lb + i * 32];
        for (int f = 0; f < Fsz; ++f) {
            const float wih = W_ih[(size_t)j * Fsz + f];
            const float* wd = W_dense + (size_t)f * Lsz + lb;
#pragma unroll
            for (int i = 0; i < 16; ++i)
                acc[i] = fmaf(wih, wd[i * 32], acc[i]);
        }
#pragma unroll
        for (int i = 0; i < 16; ++i)
            g_gp0[(size_t)j * Lsz + lb + i * 32] = acc[i];
    }
    gridbar();

    // ---- P1c: split Wcomb fp32 -> bf16 hi/lo ----
    {
        const int NT = G4L * Lsz;              // 1,048,576
        for (int idx = bid * NTHR + tid; idx < NT; idx += NCTA * NTHR) {
            __nv_bfloat16 hi, lo;
            split_bf16(g_gp0[idx], hi, lo);
            g_Bh[idx] = hi;
            g_Bl[idx] = lo;
        }
    }
    gridbar();

    // ---- load resident B tile (once): 2 halves x 128 rows x 512B ----
    {
#pragma unroll
        for (int i = 0; i < 16; ++i) {
            const int idx = tid + i * NTHR;    // 0..8191
            const int half = idx >= 4096;
            const int j = idx & 4095;
            const int row = j >> 5, q = j & 31;
            const __nv_bfloat16* src =
                (half ? g_Bl : g_Bh) + (size_t)(n0 + row) * Lsz + kb + q * 8;
            const uint32_t dst = smb + OFF_B + (uint32_t)half * BTILESZ
                               + (uint32_t)row * BPITCH + (uint32_t)q * 16;
            cpa16(dst, src);
        }
        cpa_commit();
        cpa_wait0();
        __syncthreads();
    }

    // group-private A copier: k window [kb + c*32, +32) -> group buffer bufi
    auto copyA = [&](int c, int bufi) {
        const uint32_t dst0 = smb + OFF_A + (uint32_t)((g * 2 + bufi) * GBUF);
        const int kc = kb + c * 32;
        const int r0A = m0 + wm;
#pragma unroll
        for (int i = 0; i < 2; ++i) {
            const int idx = wg_tid + i * 128;        // 0..255
            const int half = idx >> 7;
            const int j = idx & 127;
            const int row = j >> 2, q = j & 3;
            const __nv_bfloat16* src =
                (half ? g_Al : g_Ah) + (size_t)(r0A + row) * Lsz + kc + q * 8;
            cpa16(dst0 + (uint32_t)half * GSTRIP
                       + (uint32_t)row * APITCH + (uint32_t)q * 16, src);
        }
    };
    auto barg = [&]() {
        asm volatile("bar.sync %0, 128;" :: "r"(barid) : "memory");
    };

    // ---- main recurrence ----
    for (int t = 0; t < Tt; ++t) {
        float acc[2][4][4];
#pragma unroll
        for (int a = 0; a < 2; ++a)
#pragma unroll
            for (int b = 0; b < 4; ++b)
#pragma unroll
                for (int q = 0; q < 4; ++q) acc[a][b][q] = 0.f;

        copyA(0, 0);
        cpa_commit();
        cpa_wait0();
        barg();

        const int NCH = KSPL / 32;             // 8 chunks
#pragma unroll 1
        for (int c = 0; c < NCH; ++c) {
            if (c < NCH - 1) { copyA(c + 1, (c + 1) & 1); cpa_commit(); }
            const uint32_t abase = smb + OFF_A + (uint32_t)((g * 2 + (c & 1)) * GBUF);
#pragma unroll
            for (int kk = 0; kk < 2; ++kk) {
                const uint32_t koA = (uint32_t)kk * 32;
                const uint32_t koB = (uint32_t)(c * 64 + kk * 32);
                uint32_t ah[2][4], al[2][4], bh[2][4], bl[2][4];
#pragma unroll
                for (int mf = 0; mf < 2; ++mf) {
                    const uint32_t ro = (uint32_t)(mf * 16) * APITCH + laneA + koA;
                    ldsm4(ah[mf], abase + ro);
                    ldsm4(al[mf], abase + GSTRIP + ro);
                }
#pragma unroll
                for (int gg = 0; gg < 2; ++gg) {
                    const uint32_t ro = smb + OFF_B
                                      + (uint32_t)(wn + gg * 16) * BPITCH + laneB + koB;
                    ldsm4(bh[gg], ro);
                    ldsm4(bl[gg], ro + BTILESZ);
                }
                // pass 1: Ah * Bh
#pragma unroll
                for (int mf = 0; mf < 2; ++mf)
#pragma unroll
                    for (int nf = 0; nf < 4; ++nf)
                        mma16816(acc[mf][nf], ah[mf],
                                 bh[nf >> 1][(nf & 1) * 2], bh[nf >> 1][(nf & 1) * 2 + 1]);
                // pass 2: Ah * Bl
#pragma unroll
                for (int mf = 0; mf < 2; ++mf)
#pragma unroll
                    for (int nf = 0; nf < 4; ++nf)
                        mma16816(acc[mf][nf], ah[mf],
                                 bl[nf >> 1][(nf & 1) * 2], bl[nf >> 1][(nf & 1) * 2 + 1]);
                // pass 3: Al * Bh
#pragma unroll
                for (int mf = 0; mf < 2; ++mf)
#pragma unroll
                    for (int nf = 0; nf < 4; ++nf)
                        mma16816(acc[mf][nf], al[mf],
                                 bh[nf >> 1][(nf & 1) * 2], bh[nf >> 1][(nf & 1) * 2 + 1]);
            }
            if (c < NCH - 1) {
                cpa_wait0();
                barg();
            }
        }

        // epilogue: write 128x128 partial tile (each warp 32x32)
#pragma unroll
        for (int mf = 0; mf < 2; ++mf) {
            const int r0 = m0 + wm + mf * 16 + (lane >> 2);
#pragma unroll
            for (int nf = 0; nf < 4; ++nf) {
                const int col = n0 + wn + nf * 8 + (lane & 3) * 2;
                float* p = gp + (size_t)r0 * G4L + col;
                *(float2*)p             = make_float2(acc[mf][nf][0], acc[mf][nf][1]);
                *(float2*)(p + 8 * G4L) = make_float2(acc[mf][nf][2], acc[mf][nf][3]);
            }
        }
        gridbar();

        // ----- LSTM cell for rows b0..b0+3: one l-quad per thread -----
        {
            const int e = tid * 4;                  // 0..2044
            const int r = e >> 9, l = e & 511;
            const int b = b0 + r;
            const size_t gb = (size_t)b * G4L + l;
            const float4 i0 = ldcg128(&g_gp0[gb]);
            const float4 i1 = ldcg128(&g_gp1[gb]);
            const float4 f0 = ldcg128(&g_gp0[gb + 512]);
            const float4 f1 = ldcg128(&g_gp1[gb + 512]);
            const float4 g0 = ldcg128(&g_gp0[gb + 1024]);
            const float4 g1 = ldcg128(&g_gp1[gb + 1024]);
            const float4 o0 = ldcg128(&g_gp0[gb + 1536]);
            const float4 o1 = ldcg128(&g_gp1[gb + 1536]);
            const float4 bi = *(const float4*)&g_bsum[l];
            const float4 bf = *(const float4*)&g_bsum[l + 512];
            const float4 bg = *(const float4*)&g_bsum[l + 1024];
            const float4 bo = *(const float4*)&g_bsum[l + 1536];
            const size_t hc = (size_t)b * Lsz + l;
            float4 cc = *(const float4*)&g_c[hc];
            float h2q[4];
            {
                const float gi[4] = {i0.x + i1.x + bi.x, i0.y + i1.y + bi.y,
                                     i0.z + i1.z + bi.z, i0.w + i1.w + bi.w};
                const float gf[4] = {f0.x + f1.x + bf.x, f0.y + f1.y + bf.y,
                                     f0.z + f1.z + bf.z, f0.w + f1.w + bf.w};
                const float gg2[4] = {g0.x + g1.x + bg.x, g0.y + g1.y + bg.y,
                                      g0.z + g1.z + bg.z, g0.w + g1.w + bg.w};
                const float go[4] = {o0.x + o1.x + bo.x, o0.y + o1.y + bo.y,
                                     o0.z + o1.z + bo.z, o0.w + o1.w + bo.w};
                float* cp = &cc.x;
#pragma unroll
                for (int q = 0; q < 4; ++q) {
                    const float c2 = fsigmoid(gf[q]) * cp[q]
                                   + fsigmoid(gi[q]) * ftanh_(gg2[q]);
                    h2q[q] = fsigmoid(go[q]) * ftanh_(c2);
                    cp[q] = c2;
                }
            }
            *(float4*)&g_c[hc] = cc;
            *(float4*)&h2s[r * Lsz + l] = make_float4(h2q[0], h2q[1], h2q[2], h2q[3]);
            // packed bf16 hi/lo state stores (2 x STG.64)
            __nv_bfloat162 ph[2], pl[2];
#pragma unroll
            for (int q = 0; q < 2; ++q) {
                __nv_bfloat16 h0b, l0b, h1b, l1b;
                split_bf16(h2q[q * 2 + 0], h0b, l0b);
                split_bf16(h2q[q * 2 + 1], h1b, l1b);
                ph[q].x = h0b; ph[q].y = h1b;
                pl[q].x = l0b; pl[q].y = l1b;
            }
            *(uint2*)&g_Ah[hc] = *(uint2*)ph;
            *(uint2*)&g_Al[hc] = *(uint2*)pl;
        }
        __syncthreads();
        dense_part(h2s, red, b_dense, b0, out, t);
        gridbar();
    }
}

// ---------------- host ----------------------------------------------------------
extern "C" void kernel_launch(void* const* d_in, const int* in_sizes, int n_in,
                              void* d_out, int out_size) {
    const float* h0      = (const float*)d_in[0];
    const float* c0      = (const float*)d_in[1];
    const float* W_ih    = (const float*)d_in[2];
    const float* W_hh    = (const float*)d_in[3];
    const float* b_ih    = (const float*)d_in[4];
    const float* b_hh    = (const float*)d_in[5];
    const float* W_dense = (const float*)d_in[6];
    const float* b_dense = (const float*)d_in[7];
    float* out = (float*)d_out;

    cudaFuncSetAttribute(lstm_kernel,
                         cudaFuncAttributeMaxDynamicSharedMemorySize, SMEM_ALLOC);
    lstm_kernel<<<NCTA, NTHR, SMEM_ALLOC>>>(h0, c0, W_ih, W_hh, b_ih, b_hh,
                                            W_dense, b_dense, out);
}

// round 15
// speedup vs baseline: 1.7100x; 1.0188x over previous
#include <cuda_runtime.h>
#include <cuda_bf16.h>
#include <math.h>
#include <stdint.h>

#define Bsz  512
#define Lsz  512
#define Fsz  128
#define G4L  2048          // 4*L
#define KSPL 256           // K per split half (K total = 512 after Wcomb fusion)
#define Tt   512
#define OSTR (Tt * Fsz)    // out stride between batch rows
#define NCTA 128
#define NTHR 512

// ---- smem layout (dynamic, 128B-aligned base) ----
#define BPITCH  528                       // 512B data + 16B pad (conflict-free)
#define BTILESZ (128 * BPITCH)            // 67,584 per half
#define OFF_B   0
#define OFF_H2S (2 * BTILESZ)             // 135,168
#define OFF_RED (OFF_H2S + 4 * Lsz * 4)   // 143,360
#define SMEM_ALLOC (OFF_RED + 16 * 128 * 4 + 128)   // 151,680

// ---------------- device scratch ---------------------------------------------
// h state in mma-fragment layout: block (mt,kt) = 16x16 bf16 tile = 512B,
// lane i owns bytes [16i,16i+16) = regs a0,a1,a2,a3 of m16n8k16 A fragment.
__device__ uint4 g_Afh[32 * 32 * 32];        // hi half: [mt][kt][lane]
__device__ uint4 g_Afl[32 * 32 * 32];        // lo half
__device__ __nv_bfloat16 g_Bh[G4L * Lsz];    // Wcomb [j][k] (hi)
__device__ __nv_bfloat16 g_Bl[G4L * Lsz];    // (lo)
__device__ float g_WdT[Lsz * Fsz];           // [l][f] W_dense^T (fp32, out dense)
__device__ float g_bsum[G4L];                // fused bias: b_ih+b_hh+W_ih@b_d
__device__ float g_c[Bsz * Lsz];
__device__ float g_gp0[Bsz * G4L];           // partials half 0 (also Wcomb fp32 temp)
__device__ float g_gp1[Bsz * G4L];           // partials half 1
__device__ unsigned g_barcnt;
__device__ volatile unsigned g_bargen;

// ---------------- PTX helpers -------------------------------------------------
__device__ __forceinline__ uint32_t smem_u32(const void* p) {
    uint32_t a;
    asm("{ .reg .u64 t; cvta.to.shared.u64 t, %1; cvt.u32.u64 %0, t; }"
        : "=r"(a) : "l"(p));
    return a;
}
__device__ __forceinline__ void cpa16(uint32_t s, const void* g) {
    asm volatile("cp.async.cg.shared.global [%0], [%1], 16;"
                 :: "r"(s), "l"(g) : "memory");
}
__device__ __forceinline__ void cpa_commit() {
    asm volatile("cp.async.commit_group;" ::: "memory");
}
__device__ __forceinline__ void cpa_wait0() {
    asm volatile("cp.async.wait_group 0;" ::: "memory");
}
__device__ __forceinline__ void ldsm4(uint32_t* r, uint32_t addr) {
    asm volatile("ldmatrix.sync.aligned.m8n8.x4.shared.b16 {%0,%1,%2,%3}, [%4];"
                 : "=r"(r[0]), "=r"(r[1]), "=r"(r[2]), "=r"(r[3]) : "r"(addr));
}
__device__ __forceinline__ void mma16816(float* c, const uint32_t* a,
                                         uint32_t b0, uint32_t b1) {
    asm volatile(
        "mma.sync.aligned.m16n8k16.row.col.f32.bf16.bf16.f32 "
        "{%0,%1,%2,%3}, {%4,%5,%6,%7}, {%8,%9}, {%0,%1,%2,%3};"
        : "+f"(c[0]), "+f"(c[1]), "+f"(c[2]), "+f"(c[3])
        : "r"(a[0]), "r"(a[1]), "r"(a[2]), "r"(a[3]), "r"(b0), "r"(b1));
}
// L2-coherent loads (cross-CTA data in a persistent kernel; bypass stale L1)
__device__ __forceinline__ float4 ldcg128(const float* p) {
    float4 v;
    asm volatile("ld.global.cg.v4.f32 {%0,%1,%2,%3}, [%4];"
                 : "=f"(v.x), "=f"(v.y), "=f"(v.z), "=f"(v.w) : "l"(p));
    return v;
}
__device__ __forceinline__ uint4 ldcg128u(const uint4* p) {
    uint4 v;
    asm volatile("ld.global.cg.v4.u32 {%0,%1,%2,%3}, [%4];"
                 : "=r"(v.x), "=r"(v.y), "=r"(v.z), "=r"(v.w) : "l"(p));
    return v;
}

// ---------------- grid-wide barrier (pure spin) --------------------------------
__device__ __forceinline__ void gridbar() {
    __syncthreads();
    if (threadIdx.x == 0) {
        unsigned gen = g_bargen;
        __threadfence();
        if (atomicAdd(&g_barcnt, 1u) == NCTA - 1) {
            g_barcnt = 0;
            __threadfence();
            g_bargen = gen + 1;
        } else {
            while (g_bargen == gen) { }
            __threadfence();
        }
    }
    __syncthreads();
}

// ---------------- math helpers -------------------------------------------------
__device__ __forceinline__ void split_bf16(float x, __nv_bfloat16& hi,
                                           __nv_bfloat16& lo) {
    hi = __float2bfloat16(x);
    lo = __float2bfloat16(x - __bfloat162float(hi));
}
__device__ __forceinline__ float fsigmoid(float x) {
    return __fdividef(1.0f, 1.0f + __expf(-x));
}
__device__ __forceinline__ float ftanh_(float x) {
    return 1.0f - __fdividef(2.0f, __expf(2.0f * x) + 1.0f);
}
__device__ __forceinline__ uint32_t pack_bf2(float a, float b) {
    __nv_bfloat162 p;
    p.x = __float2bfloat16(a);
    p.y = __float2bfloat16(b);
    return *(uint32_t*)&p;
}

// ---------------- dense (out only): out[b][t][:] = h2s @ WdT + b_dense ---------
__device__ __forceinline__ void dense_part(const float* h2s, float* red,
                                           const float* __restrict__ b_dense,
                                           int b0, float* __restrict__ out, int t) {
    const int tid = threadIdx.x;
    const int f = tid & 127, gg = tid >> 7;     // gg in {0..3}
    float a0 = 0.f, a1 = 0.f, a2 = 0.f, a3 = 0.f;
    const int l0 = gg * 128;
#pragma unroll 4
    for (int l4 = 0; l4 < 128; l4 += 4) {
        const int l = l0 + l4;
        const float4 h0v = *(const float4*)&h2s[0 * Lsz + l];
        const float4 h1v = *(const float4*)&h2s[1 * Lsz + l];
        const float4 h2v = *(const float4*)&h2s[2 * Lsz + l];
        const float4 h3v = *(const float4*)&h2s[3 * Lsz + l];
        const float w0 = __ldg(&g_WdT[(l + 0) * Fsz + f]);
        const float w1 = __ldg(&g_WdT[(l + 1) * Fsz + f]);
        const float w2 = __ldg(&g_WdT[(l + 2) * Fsz + f]);
        const float w3 = __ldg(&g_WdT[(l + 3) * Fsz + f]);
        a0 = fmaf(h0v.x, w0, a0); a1 = fmaf(h1v.x, w0, a1);
        a2 = fmaf(h2v.x, w0, a2); a3 = fmaf(h3v.x, w0, a3);
        a0 = fmaf(h0v.y, w1, a0); a1 = fmaf(h1v.y, w1, a1);
        a2 = fmaf(h2v.y, w1, a2); a3 = fmaf(h3v.y, w1, a3);
        a0 = fmaf(h0v.z, w2, a0); a1 = fmaf(h1v.z, w2, a1);
        a2 = fmaf(h2v.z, w2, a2); a3 = fmaf(h3v.z, w2, a3);
        a0 = fmaf(h0v.w, w3, a0); a1 = fmaf(h1v.w, w3, a1);
        a2 = fmaf(h2v.w, w3, a2); a3 = fmaf(h3v.w, w3, a3);
    }
    red[(gg * 4 + 0) * 128 + f] = a0;
    red[(gg * 4 + 1) * 128 + f] = a1;
    red[(gg * 4 + 2) * 128 + f] = a2;
    red[(gg * 4 + 3) * 128 + f] = a3;
    __syncthreads();
    if (gg == 0) {
        const float bb = b_dense[f];
#pragma unroll
        for (int r = 0; r < 4; ++r) {
            const float v = red[r * 128 + f] + red[(4 + r) * 128 + f]
                          + red[(8 + r) * 128 + f] + red[(12 + r) * 128 + f] + bb;
            out[(size_t)(b0 + r) * OSTR + (size_t)t * Fsz + f] = v;
        }
    }
    __syncthreads();
}

// ---------------- the single persistent kernel ---------------------------------
__global__ void __launch_bounds__(NTHR, 1)
lstm_kernel(const float* __restrict__ h0, const float* __restrict__ c0,
            const float* __restrict__ W_ih, const float* __restrict__ W_hh,
            const float* __restrict__ b_ih, const float* __restrict__ b_hh,
            const float* __restrict__ W_dense, const float* __restrict__ b_dense,
            float* __restrict__ out) {
    extern __shared__ char dsm[];
    const uint32_t smb0 = smem_u32(dsm);
    const uint32_t smb = (smb0 + 127u) & ~127u;
    char* sbase = dsm + (smb - smb0);
    float* h2s = (float*)(sbase + OFF_H2S);
    float* red = (float*)(sbase + OFF_RED);

    const int bid = blockIdx.x, tid = threadIdx.x;
    const int wid = tid >> 5, lane = tid & 31;
    const int b0 = bid * 4;

    // gates unit: split-K halves x 64 C tiles of 128x128 (K total = 512)
    const int ks   = bid & 1;
    const int tile = bid >> 1;
    const int m0   = (tile >> 4) * 128;
    const int n0   = (tile & 15) * 128;
    const int kb   = ks * KSPL;
    float* gp = ks ? g_gp1 : g_gp0;

    // warp tile 32(m) x 32(n); warp grid 4x4
    const int wm = (wid >> 2) * 32;
    const int wn = (wid & 3) * 32;
    const uint32_t laneB = (uint32_t)((lane & 7) + ((lane >> 4) << 3)) * BPITCH
                         + (uint32_t)((lane >> 3) & 1) * 16;

    // ---- P1a: WdT, fused bias, h0 split (fragment layout), c0 copy ----
    {
        const int N1 = Lsz * Fsz;              // WdT
        const int N2 = N1 + G4L;               // fused bias
        const int N3 = N2 + Bsz * Lsz;         // h0 -> g_Afh/g_Afl
        const int N4 = N3 + Bsz * Lsz;         // c0 -> g_c
        for (int idx = bid * NTHR + tid; idx < N4; idx += NCTA * NTHR) {
            if (idx < N1) {
                const int l = idx / Fsz, f = idx % Fsz;
                g_WdT[idx] = W_dense[(size_t)f * Lsz + l];
            } else if (idx < N2) {
                const int j = idx - N1;
                float acc = b_ih[j] + b_hh[j];
                for (int f = 0; f < Fsz; ++f)
                    acc = fmaf(W_ih[(size_t)j * Fsz + f], b_dense[f], acc);
                g_bsum[j] = acc;
            } else if (idx < N3) {
                const int i = idx - N2;
                const int b = i >> 9, l = i & 511;
                __nv_bfloat16 hi, lo;
                split_bf16(h0[i], hi, lo);
                const int mt = b >> 4, mrow = b & 15;
                const int kt = l >> 4, kcol = l & 15;
                const int ln = ((mrow & 7) << 2) + ((kcol & 7) >> 1);
                const int slot = (mrow >> 3) + ((kcol >> 3) << 1);
                const int ho = (kcol & 1);
                const size_t blk = (size_t)(mt * 32 + kt) * 32;
                ((__nv_bfloat16*)&g_Afh[blk])[(ln * 4 + slot) * 2 + ho] = hi;
                ((__nv_bfloat16*)&g_Afl[blk])[(ln * 4 + slot) * 2 + ho] = lo;
            } else {
                const int i = idx - N3;
                g_c[i] = c0[i];
            }
        }
    }

    // ---- P1b: Wcomb[j][l] = W_hh[j][l] + sum_f W_ih[j][f]*W_dense[f][l] ----
    {
        const int gt = bid * NTHR + tid;       // 0..65535
        const int j  = gt >> 5;
        const int lb = gt & 31;
        float acc[16];
#pragma unroll
        for (int i = 0; i < 16; ++i)
            acc[i] = W_hh[(size_t)j * Lsz + lb + i * 32];
        for (int f = 0; f < Fsz; ++f) {
            const float wih = W_ih[(size_t)j * Fsz + f];
            const float* wd = W_dense + (size_t)f * Lsz + lb;
#pragma unroll
            for (int i = 0; i < 16; ++i)
                acc[i] = fmaf(wih, wd[i * 32], acc[i]);
        }
#pragma unroll
        for (int i = 0; i < 16; ++i)
            g_gp0[(size_t)j * Lsz + lb + i * 32] = acc[i];
    }
    gridbar();

    // ---- P1c: split Wcomb fp32 -> bf16 hi/lo ----
    {
        const int NT = G4L * Lsz;              // 1,048,576
        for (int idx = bid * NTHR + tid; idx < NT; idx += NCTA * NTHR) {
            __nv_bfloat16 hi, lo;
            split_bf16(g_gp0[idx], hi, lo);
            g_Bh[idx] = hi;
            g_Bl[idx] = lo;
        }
    }
    gridbar();

    // ---- load resident B tile (once): 2 halves x 128 rows x 512B ----
    {
#pragma unroll
        for (int i = 0; i < 16; ++i) {
            const int idx = tid + i * NTHR;    // 0..8191
            const int half = idx >= 4096;
            const int j = idx & 4095;
            const int row = j >> 5, q = j & 31;
            const __nv_bfloat16* src =
                (half ? g_Bl : g_Bh) + (size_t)(n0 + row) * Lsz + kb + q * 8;
            const uint32_t dst = smb + OFF_B + (uint32_t)half * BTILESZ
                               + (uint32_t)row * BPITCH + (uint32_t)q * 16;
            cpa16(dst, src);
        }
        cpa_commit();
        cpa_wait0();
        __syncthreads();
    }

    // A fragment pointers: warp's two 16-row m-tiles, k-tile base ks*16.
    const int mtw = (m0 + wm) >> 4;            // first m fragment tile
    const int ktb = ks * 16;
    const uint4* fh0 = g_Afh + (size_t)(mtw * 32 + ktb) * 32 + lane;
    const uint4* fh1 = g_Afh + (size_t)((mtw + 1) * 32 + ktb) * 32 + lane;
    const uint4* fl0 = g_Afl + (size_t)(mtw * 32 + ktb) * 32 + lane;
    const uint4* fl1 = g_Afl + (size_t)((mtw + 1) * 32 + ktb) * 32 + lane;

    // ---- main recurrence ----
    for (int t = 0; t < Tt; ++t) {
        float acc[2][4][4];
#pragma unroll
        for (int a = 0; a < 2; ++a)
#pragma unroll
            for (int b = 0; b < 4; ++b)
#pragma unroll
                for (int q = 0; q < 4; ++q) acc[a][b][q] = 0.f;

        // prefetch kk=0 fragments
        uint4 nh0 = ldcg128u(fh0), nh1 = ldcg128u(fh1);
        uint4 nl0 = ldcg128u(fl0), nl1 = ldcg128u(fl1);

#pragma unroll
        for (int kk = 0; kk < 16; ++kk) {
            const uint4 ch0 = nh0, ch1 = nh1, cl0 = nl0, cl1 = nl1;
            if (kk < 15) {
                nh0 = ldcg128u(fh0 + (kk + 1) * 32);
                nh1 = ldcg128u(fh1 + (kk + 1) * 32);
                nl0 = ldcg128u(fl0 + (kk + 1) * 32);
                nl1 = ldcg128u(fl1 + (kk + 1) * 32);
            }
            uint32_t bh[2][4], bl[2][4];
#pragma unroll
            for (int gg = 0; gg < 2; ++gg) {
                const uint32_t ro = smb + OFF_B
                                  + (uint32_t)(wn + gg * 16) * BPITCH + laneB
                                  + (uint32_t)kk * 32;
                ldsm4(bh[gg], ro);
                ldsm4(bl[gg], ro + BTILESZ);
            }
            const uint32_t* ah[2] = {(const uint32_t*)&ch0, (const uint32_t*)&ch1};
            const uint32_t* al[2] = {(const uint32_t*)&cl0, (const uint32_t*)&cl1};
            // pass 1: Ah * Bh
#pragma unroll
            for (int mf = 0; mf < 2; ++mf)
#pragma unroll
                for (int nf = 0; nf < 4; ++nf)
                    mma16816(acc[mf][nf], ah[mf],
                             bh[nf >> 1][(nf & 1) * 2], bh[nf >> 1][(nf & 1) * 2 + 1]);
            // pass 2: Ah * Bl
#pragma unroll
            for (int mf = 0; mf < 2; ++mf)
#pragma unroll
                for (int nf = 0; nf < 4; ++nf)
                    mma16816(acc[mf][nf], ah[mf],
                             bl[nf >> 1][(nf & 1) * 2], bl[nf >> 1][(nf & 1) * 2 + 1]);
            // pass 3: Al * Bh
#pragma unroll
            for (int mf = 0; mf < 2; ++mf)
#pragma unroll
                for (int nf = 0; nf < 4; ++nf)
                    mma16816(acc[mf][nf], al[mf],
                             bh[nf >> 1][(nf & 1) * 2], bh[nf >> 1][(nf & 1) * 2 + 1]);
        }

        // epilogue: write 128x128 partial tile (each warp 32x32)
#pragma unroll
        for (int mf = 0; mf < 2; ++mf) {
            const int r0 = m0 + wm + mf * 16 + (lane >> 2);
#pragma unroll
            for (int nf = 0; nf < 4; ++nf) {
                const int col = n0 + wn + nf * 8 + (lane & 3) * 2;
                float* p = gp + (size_t)r0 * G4L + col;
                *(float2*)p             = make_float2(acc[mf][nf][0], acc[mf][nf][1]);
                *(float2*)(p + 8 * G4L) = make_float2(acc[mf][nf][2], acc[mf][nf][3]);
            }
        }
        gridbar();

        // ----- LSTM cell for rows b0..b0+3: one l-quad per thread -----
        {
            const int e = tid * 4;                  // 0..2044
            const int r = e >> 9, l = e & 511;
            const int b = b0 + r;
            const size_t gb = (size_t)b * G4L + l;
            const float4 i0 = ldcg128(&g_gp0[gb]);
            const float4 i1 = ldcg128(&g_gp1[gb]);
            const float4 f0 = ldcg128(&g_gp0[gb + 512]);
            const float4 f1 = ldcg128(&g_gp1[gb + 512]);
            const float4 g0 = ldcg128(&g_gp0[gb + 1024]);
            const float4 g1 = ldcg128(&g_gp1[gb + 1024]);
            const float4 o0 = ldcg128(&g_gp0[gb + 1536]);
            const float4 o1 = ldcg128(&g_gp1[gb + 1536]);
            const float4 bi = *(const float4*)&g_bsum[l];
            const float4 bf = *(const float4*)&g_bsum[l + 512];
            const float4 bg = *(const float4*)&g_bsum[l + 1024];
            const float4 bo = *(const float4*)&g_bsum[l + 1536];
            const size_t hc = (size_t)b * Lsz + l;
            float4 cc = *(const float4*)&g_c[hc];
            float h2q[4];
            {
                const float gi[4] = {i0.x + i1.x + bi.x, i0.y + i1.y + bi.y,
                                     i0.z + i1.z + bi.z, i0.w + i1.w + bi.w};
                const float gf[4] = {f0.x + f1.x + bf.x, f0.y + f1.y + bf.y,
                                     f0.z + f1.z + bf.z, f0.w + f1.w + bf.w};
                const float gg2[4] = {g0.x + g1.x + bg.x, g0.y + g1.y + bg.y,
                                      g0.z + g1.z + bg.z, g0.w + g1.w + bg.w};
                const float go[4] = {o0.x + o1.x + bo.x, o0.y + o1.y + bo.y,
                                     o0.z + o1.z + bo.z, o0.w + o1.w + bo.w};
                float* cp = &cc.x;
#pragma unroll
                for (int q = 0; q < 4; ++q) {
                    const float c2 = fsigmoid(gf[q]) * cp[q]
                                   + fsigmoid(gi[q]) * ftanh_(gg2[q]);
                    h2q[q] = fsigmoid(go[q]) * ftanh_(c2);
                    cp[q] = c2;
                }
            }
            *(float4*)&g_c[hc] = cc;
            *(float4*)&h2s[r * Lsz + l] = make_float4(h2q[0], h2q[1], h2q[2], h2q[3]);
            // fragment-layout state stores (4 x STG.32)
            {
                const int mt = b >> 4, mrow = b & 15;
                const int kt = l >> 4, kcol = l & 15;   // kcol in {0,4,8,12}
                const int ln = ((mrow & 7) << 2) + ((kcol & 7) >> 1);
                const int slot = (mrow >> 3) + ((kcol >> 3) << 1);
                const size_t blk = (size_t)(mt * 32 + kt) * 32;
                uint32_t* bhp = (uint32_t*)&g_Afh[blk];
                uint32_t* blp = (uint32_t*)&g_Afl[blk];
                float hi0, hi1, hi2, hi3, lo0, lo1, lo2, lo3;
                {
                    __nv_bfloat16 h, lo;
                    split_bf16(h2q[0], h, lo); hi0 = __bfloat162float(h); lo0 = __bfloat162float(lo);
                    split_bf16(h2q[1], h, lo); hi1 = __bfloat162float(h); lo1 = __bfloat162float(lo);
                    split_bf16(h2q[2], h, lo); hi2 = __bfloat162float(h); lo2 = __bfloat162float(lo);
                    split_bf16(h2q[3], h, lo); hi3 = __bfloat162float(h); lo3 = __bfloat162float(lo);
                }
                bhp[ln * 4 + slot]       = pack_bf2(hi0, hi1);
                bhp[(ln + 1) * 4 + slot] = pack_bf2(hi2, hi3);
                blp[ln * 4 + slot]       = pack_bf2(lo0, lo1);
                blp[(ln + 1) * 4 + slot] = pack_bf2(lo2, lo3);
            }
        }
        __syncthreads();
        dense_part(h2s, red, b_dense, b0, out, t);
        gridbar();
    }
}

// ---------------- host ----------------------------------------------------------
extern "C" void kernel_launch(void* const* d_in, const int* in_sizes, int n_in,
                              void* d_out, int out_size) {
    const float* h0      = (const float*)d_in[0];
    const float* c0      = (const float*)d_in[1];
    const float* W_ih    = (const float*)d_in[2];
    const float* W_hh    = (const float*)d_in[3];
    const float* b_ih    = (const float*)d_in[4];
    const float* b_hh    = (const float*)d_in[5];
    const float* W_dense = (const float*)d_in[6];
    const float* b_dense = (const float*)d_in[7];
    float* out = (float*)d_out;

    cudaFuncSetAttribute(lstm_kernel,
                         cudaFuncAttributeMaxDynamicSharedMemorySize, SMEM_ALLOC);
    lstm_kernel<<<NCTA, NTHR, SMEM_ALLOC>>>(h0, c0, W_ih, W_hh, b_ih, b_hh,
                                            W_dense, b_dense, out);
}